// round 15
// baseline (speedup 1.0000x reference)
#include <cuda_runtime.h>
typedef unsigned int u32;

#define HH 4096
#define ROWF 12288          // floats per image row
#define TPB 256             // one thread per PIXEL (all 3 channels)
#define RSP 792             // floats per staged row ((256+8 halo)*3)
#define BUFF 3168           // floats per 4-row stage buffer
#define BUFB 12672          // bytes per 4-row stage buffer
#define SMEMB 50688         // 4 stage buffers

// radius-1 taps renormalized to unit applied mass (sigma=0.5, 25-tap reference
// window; dropped taps carry 5.3e-4 of mass). Used for BOTH directions.
#define KB0 0.78698593f
#define KB1 0.10650699f
#define DECAYf 0.60653065971263342f
#define OMDf   0.39346934028736658f
#define INV3f  0.33333322222f        // 1/(3 + 1e-6)

__global__ __launch_bounds__(TPB, 4)
void chem_kernel(const float* __restrict__ D, const float* __restrict__ Cm,
                 float* __restrict__ out)
{
    extern __shared__ float stage[];     // 4 bufs x 4 rows x 792 floats

    const int tid = threadIdx.x;         // pixel within strip
    const int w0  = blockIdx.x << 8;     // 16 strips of 256 cols
    const int by  = blockIdx.y;          // 37 chunks: 26 of 111 rows + 11 of 110
    const int h0   = (by < 26) ? 111 * by : 2886 + 110 * (by - 26);
    const int hend = h0 + ((by < 26) ? 111 : 110);

    float cm[9];
#pragma unroll
    for (int i = 0; i < 9; ++i) cm[i] = __ldg(Cm + i);

    // cp.async loader: 792 float4 per 4-row batch -> mappings m=0..2 full, m=3 tid<24
    int lj[4], lg[4], lsa_[4]; bool lok[4];
    {
        const u32 sb0 = (u32)__cvta_generic_to_shared(stage);
#pragma unroll
        for (int m = 0; m < 4; ++m) {
            const int idx = tid + m * TPB;
            const int j = idx / 198, v = idx - 198 * j;
            lj[m] = j;
            const int g = (w0 - 4) * 3 + 4 * v;
            lg[m] = g;
            lok[m] = (g >= 0) && (g + 4 <= ROWF);
            lsa_[m] = (int)(sb0 + (u32)((j * RSP + 4 * v) * 4));
        }
    }

    // per-channel register state (radius-1 both dims, lag-1 output)
    float hb[3][4];                      // horizontal-blur ring, slot = J
#pragma unroll
    for (int c = 0; c < 3; ++c)
#pragma unroll
        for (int k = 0; k < 4; ++k) hb[c][k] = 0.f;
    float dr[3][2], sr[3][2];            // lag-1 density / soft rings
#pragma unroll
    for (int c = 0; c < 3; ++c) { dr[c][0]=dr[c][1]=sr[c][0]=sr[c][1]=0.f; }
    float s3[3] = {0.f, 0.f, 0.f};       // IIR states

    int rb = h0 - 23;                    // 34 batches of 4 rows; emit from k=6
    float* opt = out + h0 * ROWF + (w0 + tid) * 3;

#define CPA(M, RB, SB) { \
    const int row = (RB) + lj[M]; \
    const int sz  = (lok[M] && row >= 0 && row < HH) ? 16 : 0; \
    const float* gp = sz ? (D + row * ROWF + lg[M]) : D; \
    asm volatile("cp.async.cg.shared.global [%0], [%1], 16, %2;\n" \
                 :: "r"((u32)lsa_[M] + (u32)(SB) * BUFB), "l"(gp), "r"(sz) : "memory"); }

#define ISSUE(RB, SB) { \
    CPA(0, RB, SB) CPA(1, RB, SB) CPA(2, RB, SB) \
    if (tid < 24) CPA(3, RB, SB) \
    asm volatile("cp.async.commit_group;\n" ::: "memory"); }

// Row J of batch (r = rb+J); output row ro = r-1. Slot J holds row r; row r-1
// in slot (J+3)&3, r-2 in (J+2)&3. dr/sr: slot J&1 holds r, (J+1)&1 holds r-1.
// 9 contiguous stage floats (cols p-1,p,p+1 x 3ch): stride-3 lanes, gcd(3,32)=1
// -> conflict-free LDS. Channel mix + tanh + store fully in registers.
#define ROWB(J, EMIT, PRED) { \
    const float xl0 = bps[(J)*RSP+ 9], xl1 = bps[(J)*RSP+10], xl2 = bps[(J)*RSP+11]; \
    const float xc0 = bps[(J)*RSP+12], xc1 = bps[(J)*RSP+13], xc2 = bps[(J)*RSP+14]; \
    const float xr0 = bps[(J)*RSP+15], xr1 = bps[(J)*RSP+16], xr2 = bps[(J)*RSP+17]; \
    s3[0] = fmaf(DECAYf, s3[0], xc0); \
    s3[1] = fmaf(DECAYf, s3[1], xc1); \
    s3[2] = fmaf(DECAYf, s3[2], xc2); \
    hb[0][(J)&3] = fmaf(xl0 + xr0, KB1, xc0 * KB0); \
    hb[1][(J)&3] = fmaf(xl1 + xr1, KB1, xc1 * KB0); \
    hb[2][(J)&3] = fmaf(xl2 + xr2, KB1, xc2 * KB0); \
    if (EMIT) { \
        float ih[3], dd[3]; \
        _Pragma("unroll") \
        for (int c = 0; c < 3; ++c) { \
            const float vb = fmaf(hb[c][((J)+2)&3] + hb[c][(J)&3], KB1, \
                                  hb[c][((J)+3)&3] * KB0); \
            dd[c] = dr[c][((J)+1)&1]; \
            const float s_ = sr[c][((J)+1)&1]; \
            ih[c] = s_ + (dd[c] * INV3f) * (vb - s_); \
        } \
        _Pragma("unroll") \
        for (int j = 0; j < 3; ++j) { \
            const float inh = cm[j]*ih[0] + cm[3+j]*ih[1] + cm[6+j]*ih[2]; \
            const float arg = (dd[j] - inh) * INV3f; \
            float t; asm("tanh.approx.f32 %0, %1;" : "=f"(t) : "f"(arg)); \
            if (!(PRED) || (rb + (J) - 1 < hend)) \
                __stcs(opt + (J) * ROWF + j, 3.0f * t); \
        } \
    } \
    dr[0][(J)&1] = xc0; dr[1][(J)&1] = xc1; dr[2][(J)&1] = xc2; \
    sr[0][(J)&1] = OMDf * s3[0]; \
    sr[1][(J)&1] = OMDf * s3[1]; \
    sr[2][(J)&1] = OMDf * s3[2]; }

#define CPWAIT(N) asm volatile("cp.async.wait_group " #N ";\n" ::: "memory")

// ONE barrier per batch; buf (SB+2)&3 was fully read two batches ago.
#define BB(SB, EMIT, ISS, WN, PRED) { \
    CPWAIT(WN); __syncthreads(); \
    if (ISS) ISSUE(rb + 8, ((SB)+2)&3) \
    const float* bps = stage + (SB) * BUFF + 3 * tid; \
    ROWB(0, EMIT, PRED) ROWB(1, EMIT, PRED) \
    ROWB(2, EMIT, PRED) ROWB(3, EMIT, PRED) \
    rb += 4; if (EMIT) opt += 4 * ROWF; }

    // prologue: batches 0,1 in flight
    ISSUE(rb,     0)
    ISSUE(rb + 4, 1)

    // warm-up: batches 0..5 (rows h0-23 .. h0; emits would be < h0)
    BB(0, 0,1,1,0) BB(1, 0,1,1,0) BB(2, 0,1,1,0)
    BB(3, 0,1,1,0) BB(0, 0,1,1,0) BB(1, 0,1,1,0)

    // emit: batches 6..29 (ro = h0 .. h0+95)
#pragma unroll 1
    for (int p = 0; p < 6; ++p) {
        BB(2, 1,1,1,0) BB(3, 1,1,1,0) BB(0, 1,1,1,0) BB(1, 1,1,1,0)
    }

    // k=30,31 (last ISSUEs -> batches 32,33), k=32, k=33 (tail predicated)
    BB(2, 1,1,1,0) BB(3, 1,1,1,0)
    BB(0, 1,0,1,0)
    BB(1, 1,0,0,1)

#undef BB
#undef CPWAIT
#undef ROWB
#undef ISSUE
#undef CPA
}

extern "C" void kernel_launch(void* const* d_in, const int* in_sizes, int n_in,
                              void* d_out, int out_size)
{
    const float* D   = (const float*)d_in[0];   // (4096, 4096, 3) f32
    const float* Cm  = (const float*)d_in[1];   // (3, 3) f32
    float*       out = (float*)d_out;           // (4096, 4096, 3) f32
    cudaFuncSetAttribute(chem_kernel, cudaFuncAttributeMaxDynamicSharedMemorySize, SMEMB);
    dim3 grid(16, 37);                          // 592 blocks = 4/SM x 148 SMs
    chem_kernel<<<grid, TPB, SMEMB>>>(D, Cm, out);
}